// round 16
// baseline (speedup 1.0000x reference)
#include <cuda_runtime.h>
#include <cuda_fp16.h>
#include <cstdint>

// ---------------- problem constants ----------------
#define BB 4
#define CC 256
#define HH 96
#define WW 320
#define HW (HH * WW)          // 30720
#define MT 64                 // queries per tile
#define NCHUNK 8              // 8 chunks of 32 channels (2 ksteps)
#define NTH 384               // 8 consumer warps + 4 producer warps
#define NCONS 256             // consumer thread count
#define RAD 4
#define NCH 36
#define NTILES (5 * HH * BB)  // 1920

// ---------------- stage layout (bytes), per 2-kstep stage ----------------
#define BSTR 656              // B row stride: 328 halves (41*16B, conflict-free)
#define ASTR 176              // A row stride: 88 halves (11*16B)
#define OFF_B 0
#define OFF_A (32 * BSTR)              // 20992
#define STAGE_BYTES (OFF_A + 32 * ASTR)    // 26624 (x2 stages = 53248)
#define KS_B (16 * BSTR)
#define KS_A (16 * ASTR)

// ---------------- vol layout (floats), separate from stages ----------------
#define GUARD 80
#define VROW 484
#define VOL_OFF (2 * STAGE_BYTES)          // 53248
#define VOL_BYTES (MT * VROW * 4)          // 123904
#define SMEM_BYTES (VOL_OFF + VOL_BYTES)   // 177152

static __device__ __forceinline__ uint32_t smem_u32(const void* p) {
    uint32_t a;
    asm("{ .reg .u64 t; cvta.to.shared.u64 t, %1; cvt.u32.u64 %0, t; }" : "=r"(a) : "l"(p));
    return a;
}
static __device__ __forceinline__ void ldsm4t(uint32_t* r, uint32_t a) {
    asm volatile("ldmatrix.sync.aligned.m8n8.x4.trans.shared.b16 {%0,%1,%2,%3}, [%4];"
                 : "=r"(r[0]), "=r"(r[1]), "=r"(r[2]), "=r"(r[3]) : "r"(a));
}
static __device__ __forceinline__ void ldsm2t(uint32_t* r, uint32_t a) {
    asm volatile("ldmatrix.sync.aligned.m8n8.x2.trans.shared.b16 {%0,%1}, [%2];"
                 : "=r"(r[0]), "=r"(r[1]) : "r"(a));
}
static __device__ __forceinline__ void mma16816(float* d, const uint32_t* a, const uint32_t* b) {
    asm volatile("mma.sync.aligned.m16n8k16.row.col.f32.f16.f16.f32 "
                 "{%0,%1,%2,%3}, {%4,%5,%6,%7}, {%8,%9}, {%0,%1,%2,%3};"
                 : "+f"(d[0]), "+f"(d[1]), "+f"(d[2]), "+f"(d[3])
                 : "r"(a[0]), "r"(a[1]), "r"(a[2]), "r"(a[3]), "r"(b[0]), "r"(b[1]));
}
static __device__ __forceinline__ void cvt_sts4(uint32_t addr, float4 x) {
    uint32_t p0, p1;
    asm("cvt.rn.f16x2.f32 %0, %1, %2;" : "=r"(p0) : "f"(x.y), "f"(x.x));
    asm("cvt.rn.f16x2.f32 %0, %1, %2;" : "=r"(p1) : "f"(x.w), "f"(x.z));
    asm volatile("st.shared.v2.b32 [%0], {%1,%2};" :: "r"(addr), "r"(p0), "r"(p1) : "memory");
}

__global__ void __launch_bounds__(NTH, 1)
corr_hmma_kernel(const float* __restrict__ fmap1, const float* __restrict__ fmap2,
                 const float* __restrict__ cents, float* __restrict__ out) {
    extern __shared__ char smem[];
    const uint32_t sb = smem_u32(smem);
    const int t = threadIdx.x, wid = t >> 5, lid = t & 31;
    const bool isCons = (t < NCONS);

    // ---- consumer: per-lane ldmatrix offsets ----
    const int r8 = lid & 7, tl = lid >> 3;
    const uint32_t laneA = (uint32_t)((r8 + 8 * (tl >> 1)) * ASTR + (tl & 1) * 16);
    const uint32_t laneB = (uint32_t)((r8 + 8 * (tl & 1)) * BSTR + (tl >> 1) * 16);
    const uint32_t nbase = (uint32_t)(80 * (wid & 7));  // n = 40*wid for consumers

    // ---- producer: mapping pt -> (channel-in-kstep, pos8) ----
    const int pt  = isCons ? 0 : (t - NCONS);   // 0..127
    const int chp = pt >> 3;                    // 0..15
    const int p8  = pt & 7;                     // 0..7
    const uint32_t sts_a0 = sb + OFF_A + (uint32_t)(chp * ASTR + 8 * p8);
    const uint32_t sts_bp = sb + OFF_B + (uint32_t)(chp * BSTR + 8 * p8);

    float* vol = (float*)(smem + VOL_OFF);

    // ---- zero vol guards once (consumers) ----
    if (isCons) {
        const int row = t >> 2, part = t & 3;
        float4 z = make_float4(0.f, 0.f, 0.f, 0.f);
        float4* rp = (float4*)(vol + row * VROW);
#pragma unroll
        for (int i = 0; i < 5; ++i) rp[part + 4 * i] = z;
#pragma unroll
        for (int i = 0; i < 6; ++i) {
            const int idx = 100 + part + 4 * i;
            if (idx < 121) rp[idx] = z;
        }
    }

    int tile = blockIdx.x;
    int qt = tile % 5, rm = tile / 5, hh = rm % HH, bb2 = rm / HH;
    int q0 = qt * MT;

    // producer global pointers for current tile
    const float* Agp = fmap1 + ((size_t)bb2 * CC + chp) * HW + (size_t)hh * WW + q0 + 4 * p8;
    const float* Bgp = fmap2 + ((size_t)bb2 * CC + chp) * HW + (size_t)hh * WW + 4 * p8;

    float4 ra[2][2], rbp[2][10];

#define P_LDG(cb, pA, pB) do {                                                  \
    _Pragma("unroll") for (int ks = 0; ks < 2; ++ks) {                          \
        const size_t o = (size_t)((cb) + 16 * ks) * HW;                         \
        ra[ks][0] = *(const float4*)((pA) + o);                                 \
        ra[ks][1] = *(const float4*)((pA) + o + 32);                            \
        _Pragma("unroll") for (int i = 0; i < 10; ++i)                          \
            rbp[ks][i] = *(const float4*)((pB) + o + 32 * i);                   \
    } } while (0)

#define P_STS(bufoff) do {                                                      \
    _Pragma("unroll") for (int ks = 0; ks < 2; ++ks) {                          \
        const uint32_t ka = (uint32_t)(bufoff) + (uint32_t)(ks * KS_A);         \
        const uint32_t kb = (uint32_t)(bufoff) + (uint32_t)(ks * KS_B);         \
        cvt_sts4(sts_a0 + ka, ra[ks][0]);                                       \
        cvt_sts4(sts_a0 + ka + 64u, ra[ks][1]);                                 \
        _Pragma("unroll") for (int i = 0; i < 10; ++i)                          \
            cvt_sts4(sts_bp + kb + 64u * i, rbp[ks][i]);                        \
    } } while (0)

    // ---- prologue: producers stage chunk 0, prefetch chunk 1 ----
    if (!isCons) {
        P_LDG(0, Agp, Bgp);
        P_STS(0);
        P_LDG(32, Agp, Bgp);
    }
    __syncthreads();

    for (;;) {
        const int ntile = tile + (int)gridDim.x;
        const bool have_next = (ntile < NTILES);
        int nq0 = q0, nhh = hh, nbb = bb2;
        const float *nAgp = Agp, *nBgp = Bgp;
        if (have_next) {
            const int nqt = ntile % 5, nrm = ntile / 5;
            nhh = nrm % HH; nbb = nrm / HH; nq0 = nqt * MT;
            if (!isCons) {
                nAgp = fmap1 + ((size_t)nbb * CC + chp) * HW + (size_t)nhh * WW + nq0 + 4 * p8;
                nBgp = fmap2 + ((size_t)nbb * CC + chp) * HW + (size_t)nhh * WW + 4 * p8;
            }
        }

        // consumer: prefetch centroid for sampling (hidden under mainloop)
        float cent = 0.0f;
        if (isCons) cent = cents[((size_t)bb2 * HH + hh) * WW + q0 + (t & 63)];

        float acc[4][5][4];
        if (isCons) {
#pragma unroll
            for (int i = 0; i < 4; ++i)
#pragma unroll
                for (int j = 0; j < 5; ++j)
#pragma unroll
                    for (int k2 = 0; k2 < 4; ++k2) acc[i][j][k2] = 0.0f;
        }

        // ---- mainloop: 8 phases, role-split, one barrier per phase ----
        for (int c = 0; c < NCHUNK; ++c) {
            if (isCons) {
                const uint32_t cur = sb + (uint32_t)((c & 1) * STAGE_BYTES);
                // kstep 0
                uint32_t a0[4][4], b0[10];
                {
                    const uint32_t ab = cur + OFF_A + laneA;
#pragma unroll
                    for (int i = 0; i < 4; ++i) ldsm4t(a0[i], ab + 32u * i);
                    const uint32_t bbq = cur + OFF_B + laneB + nbase;
                    ldsm4t(b0 + 0, bbq); ldsm4t(b0 + 4, bbq + 32u); ldsm2t(b0 + 8, bbq + 64u);
                }
#pragma unroll
                for (int i = 0; i < 4; ++i)
#pragma unroll
                    for (int j = 0; j < 5; ++j)
                        mma16816(acc[i][j], a0[i], b0 + 2 * j);
                // kstep 1
                uint32_t a1[4][4], b1[10];
                {
                    const uint32_t ab = cur + OFF_A + (uint32_t)KS_A + laneA;
#pragma unroll
                    for (int i = 0; i < 4; ++i) ldsm4t(a1[i], ab + 32u * i);
                    const uint32_t bbq = cur + OFF_B + (uint32_t)KS_B + laneB + nbase;
                    ldsm4t(b1 + 0, bbq); ldsm4t(b1 + 4, bbq + 32u); ldsm2t(b1 + 8, bbq + 64u);
                }
#pragma unroll
                for (int i = 0; i < 4; ++i)
#pragma unroll
                    for (int j = 0; j < 5; ++j)
                        mma16816(acc[i][j], a1[i], b1 + 2 * j);
            } else {
                if (c < NCHUNK - 1) {
                    P_STS(((c + 1) & 1) * STAGE_BYTES);   // stage chunk c+1
                    if (c + 2 < NCHUNK) {
                        P_LDG((c + 2) * 32, Agp, Bgp);     // chunk c+2
                    } else if (have_next) {
                        P_LDG(0, nAgp, nBgp);              // next tile chunk 0
                    }
                } else {
                    if (have_next) {
                        P_STS(0);                          // next tile chunk 0 -> buf0
                        P_LDG(32, nAgp, nBgp);             // next tile chunk 1
                    }
                }
            }
            __syncthreads();
        }

        // ---- epilogue: consumers write acc -> vol ----
        if (isCons) {
            const int mr = lid >> 2, nc0 = 2 * (lid & 3);
            const float s = 0.0625f;  // 1/sqrt(256)
#pragma unroll
            for (int i = 0; i < 4; ++i)
#pragma unroll
                for (int j = 0; j < 5; ++j) {
                    const int q = 16 * i + mr, v = 40 * (wid & 7) + 8 * j + nc0;
                    *(float2*)&vol[q * VROW + GUARD + v] =
                        make_float2(acc[i][j][0] * s, acc[i][j][1] * s);
                    *(float2*)&vol[(q + 8) * VROW + GUARD + v] =
                        make_float2(acc[i][j][2] * s, acc[i][j][3] * s);
                }
        }
        __syncthreads();

        // ---- pyramid sampling (consumers): thread = (q, level) ----
        if (isCons) {
            const int q = t & 63, lvl = t >> 6;
            const float inv = 1.0f / (float)(1 << lvl);
            const float xl = cent * inv - (float)RAD;
            const float fl = floorf(xl);
            const int i0 = (int)fl;
            const float tt = xl - fl;
            const float* p = vol + q * VROW + GUARD + i0 * (1 << lvl);

            float S[10];
            if (lvl == 0) {
#pragma unroll
                for (int d = 0; d < 10; ++d) S[d] = p[d];
            } else if (lvl == 1) {
#pragma unroll
                for (int d = 0; d < 10; ++d) {
                    float2 v = ((const float2*)p)[d];
                    S[d] = v.x + v.y;
                }
            } else if (lvl == 2) {
#pragma unroll
                for (int d = 0; d < 10; ++d) {
                    float4 v = ((const float4*)p)[d];
                    S[d] = (v.x + v.y) + (v.z + v.w);
                }
            } else {
#pragma unroll
                for (int d = 0; d < 10; ++d) {
                    float4 v0 = ((const float4*)p)[2 * d];
                    float4 v1 = ((const float4*)p)[2 * d + 1];
                    S[d] = ((v0.x + v0.y) + (v0.z + v0.w)) + ((v1.x + v1.y) + (v1.z + v1.w));
                }
            }
            float* ob = out + (((size_t)bb2 * NCH + lvl * 9) * HH + hh) * WW + q0 + q;
#pragma unroll
            for (int d = 0; d < 9; ++d)
                ob[(size_t)d * HW] = (S[d] * (1.0f - tt) + S[d + 1] * tt) * inv;
        }

        if (!have_next) break;
        tile = ntile; q0 = nq0; hh = nhh; bb2 = nbb; Agp = nAgp; Bgp = nBgp;
        // stage0 already holds next tile's chunk 0 (staged in phase 7);
        // producers' regs hold chunk 1. Phase 0 of next tile proceeds directly.
    }
}

extern "C" void kernel_launch(void* const* d_in, const int* in_sizes, int n_in,
                              void* d_out, int out_size) {
    const float* fmap1 = (const float*)d_in[0];
    const float* fmap2 = (const float*)d_in[1];
    const float* cents = (const float*)d_in[2];
    float* out = (float*)d_out;

    cudaFuncSetAttribute(corr_hmma_kernel,
                         cudaFuncAttributeMaxDynamicSharedMemorySize, SMEM_BYTES);

    int dev = 0, sms = 148;
    cudaGetDevice(&dev);
    cudaDeviceGetAttribute(&sms, cudaDevAttrMultiProcessorCount, dev);
    if (sms > NTILES) sms = NTILES;

    corr_hmma_kernel<<<sms, NTH, SMEM_BYTES>>>(fmap1, fmap2, cents, out);
}

// round 17
// speedup vs baseline: 2.2498x; 2.2498x over previous
#include <cuda_runtime.h>
#include <cuda_fp16.h>
#include <cstdint>

// ---------------- problem constants ----------------
#define BB 4
#define CC 256
#define HH 96
#define WW 320
#define HW (HH * WW)          // 30720
#define MT 64                 // queries per tile
#define NCHUNK 8              // 8 chunks of 32 channels (2 ksteps)
#define NTH 256
#define RAD 4
#define NCH 36
#define NTILES (5 * HH * BB)  // 1920

// ---------------- stage layout (bytes), per 2-kstep stage ----------------
#define BSTR 656              // B row stride: 328 halves (41*16B, conflict-free)
#define ASTR 176              // A row stride: 88 halves (11*16B)
#define OFF_B 0
#define OFF_A (32 * BSTR)              // 20992
#define STAGE_BYTES (OFF_A + 32 * ASTR)    // 26624 (x2 stages = 53248)
#define KS_B (16 * BSTR)
#define KS_A (16 * ASTR)

// ---------------- vol layout (floats), separate from stages ----------------
#define GUARD 80
#define VROW 484
#define VOL_OFF (2 * STAGE_BYTES)          // 53248
#define VOL_BYTES (MT * VROW * 4)          // 123904
#define SMEM_BYTES (VOL_OFF + VOL_BYTES)   // 177152

static __device__ __forceinline__ uint32_t smem_u32(const void* p) {
    uint32_t a;
    asm("{ .reg .u64 t; cvta.to.shared.u64 t, %1; cvt.u32.u64 %0, t; }" : "=r"(a) : "l"(p));
    return a;
}
static __device__ __forceinline__ void ldsm4t(uint32_t* r, uint32_t a) {
    asm volatile("ldmatrix.sync.aligned.m8n8.x4.trans.shared.b16 {%0,%1,%2,%3}, [%4];"
                 : "=r"(r[0]), "=r"(r[1]), "=r"(r[2]), "=r"(r[3]) : "r"(a));
}
static __device__ __forceinline__ void ldsm2t(uint32_t* r, uint32_t a) {
    asm volatile("ldmatrix.sync.aligned.m8n8.x2.trans.shared.b16 {%0,%1}, [%2];"
                 : "=r"(r[0]), "=r"(r[1]) : "r"(a));
}
static __device__ __forceinline__ void mma16816(float* d, const uint32_t* a, const uint32_t* b) {
    asm volatile("mma.sync.aligned.m16n8k16.row.col.f32.f16.f16.f32 "
                 "{%0,%1,%2,%3}, {%4,%5,%6,%7}, {%8,%9}, {%0,%1,%2,%3};"
                 : "+f"(d[0]), "+f"(d[1]), "+f"(d[2]), "+f"(d[3])
                 : "r"(a[0]), "r"(a[1]), "r"(a[2]), "r"(a[3]), "r"(b[0]), "r"(b[1]));
}
static __device__ __forceinline__ void cvt_sts4(uint32_t addr, float4 x) {
    uint32_t p0, p1;
    asm("cvt.rn.f16x2.f32 %0, %1, %2;" : "=r"(p0) : "f"(x.y), "f"(x.x));
    asm("cvt.rn.f16x2.f32 %0, %1, %2;" : "=r"(p1) : "f"(x.w), "f"(x.z));
    asm volatile("st.shared.v2.b32 [%0], {%1,%2};" :: "r"(addr), "r"(p0), "r"(p1) : "memory");
}

// Sample one tile's 36x64 outputs from vol (rel. coords captured in args).
static __device__ __forceinline__ void do_sampling(
    const float* __restrict__ vol, float* __restrict__ out,
    float cent, int t, int q0, int hh, int bb2) {
    const int q = t & 63, lvl = t >> 6;
    const float inv = 1.0f / (float)(1 << lvl);
    const float xl = cent * inv - (float)RAD;
    const float fl = floorf(xl);
    const int i0 = (int)fl;
    const float tt = xl - fl;
    const float* p = vol + q * VROW + GUARD + i0 * (1 << lvl);

    float S[10];
    if (lvl == 0) {
#pragma unroll
        for (int d = 0; d < 10; ++d) S[d] = p[d];
    } else if (lvl == 1) {
#pragma unroll
        for (int d = 0; d < 10; ++d) {
            float2 v = ((const float2*)p)[d];
            S[d] = v.x + v.y;
        }
    } else if (lvl == 2) {
#pragma unroll
        for (int d = 0; d < 10; ++d) {
            float4 v = ((const float4*)p)[d];
            S[d] = (v.x + v.y) + (v.z + v.w);
        }
    } else {
#pragma unroll
        for (int d = 0; d < 10; ++d) {
            float4 v0 = ((const float4*)p)[2 * d];
            float4 v1 = ((const float4*)p)[2 * d + 1];
            S[d] = ((v0.x + v0.y) + (v0.z + v0.w)) + ((v1.x + v1.y) + (v1.z + v1.w));
        }
    }
    float* ob = out + (((size_t)bb2 * NCH + lvl * 9) * HH + hh) * WW + q0 + q;
#pragma unroll
    for (int d = 0; d < 9; ++d)
        ob[(size_t)d * HW] = (S[d] * (1.0f - tt) + S[d + 1] * tt) * inv;
}

__global__ void __launch_bounds__(NTH, 1)
corr_hmma_kernel(const float* __restrict__ fmap1, const float* __restrict__ fmap2,
                 const float* __restrict__ cents, float* __restrict__ out) {
    extern __shared__ char smem[];
    const uint32_t sb = smem_u32(smem);
    const int t = threadIdx.x, wid = t >> 5, lid = t & 31;

    // ---- staging mapping: thread -> (channel-in-kstep, float4 position) ----
    const int ch  = t >> 4;   // 0..15
    const int pos = t & 15;   // 0..15

    // ---- per-lane ldmatrix offsets ----
    const int r8 = lid & 7, tl = lid >> 3;
    const uint32_t laneA = (uint32_t)((r8 + 8 * (tl >> 1)) * ASTR + (tl & 1) * 16);
    const uint32_t laneB = (uint32_t)((r8 + 8 * (tl & 1)) * BSTR + (tl >> 1) * 16);
    const uint32_t nbase = (uint32_t)(80 * wid);

    const uint32_t sts_a = sb + OFF_A + (uint32_t)(ch * ASTR + 8 * pos);
    const uint32_t sts_b = sb + OFF_B + (uint32_t)(ch * BSTR + 8 * pos);

    float* vol = (float*)(smem + VOL_OFF);

    // ---- zero vol guards once ----
    {
        const int row = t >> 2, part = t & 3;
        float4 z = make_float4(0.f, 0.f, 0.f, 0.f);
        float4* rp = (float4*)(vol + row * VROW);
#pragma unroll
        for (int i = 0; i < 5; ++i) rp[part + 4 * i] = z;
#pragma unroll
        for (int i = 0; i < 6; ++i) {
            const int idx = 100 + part + 4 * i;
            if (idx < 121) rp[idx] = z;
        }
    }

    int tile = blockIdx.x;
    if (tile >= NTILES) return;

    int qt = tile % 5, rm = tile / 5, hh = rm % HH, bb2 = rm / HH;
    int q0 = qt * MT;
    const float* Ag = fmap1 + ((size_t)bb2 * CC + ch) * HW + (size_t)hh * WW + q0 + 4 * pos;
    const float* Bg = fmap2 + ((size_t)bb2 * CC + ch) * HW + (size_t)hh * WW + 4 * pos;

    // chunk-0 LDGs for first tile
    float4 ra[2], rb[2][5];
#pragma unroll
    for (int ks = 0; ks < 2; ++ks) {
        const size_t o = (size_t)(16 * ks) * HW;
        ra[ks] = *(const float4*)(Ag + o);
#pragma unroll
        for (int j = 0; j < 5; ++j) rb[ks][j] = *(const float4*)(Bg + o + 64 * j);
    }

    // previous-tile sampling context
    bool have_prev = false;
    float pcent = 0.0f;
    int pq0 = 0, phh = 0, pbb = 0;

    for (;;) {
        // cent for current tile (consumed at next iteration's phase 0)
        const float cent = cents[((size_t)bb2 * HH + hh) * WW + q0 + (t & 63)];

        // ---- stage chunk 0 (from regs); LDG chunk 1 into regs ----
#pragma unroll
        for (int ks = 0; ks < 2; ++ks) {
            cvt_sts4(sts_a + (uint32_t)(ks * KS_A), ra[ks]);
#pragma unroll
            for (int j = 0; j < 5; ++j)
                cvt_sts4(sts_b + (uint32_t)(ks * KS_B) + 128u * j, rb[ks][j]);
        }
#pragma unroll
        for (int ks = 0; ks < 2; ++ks) {
            const size_t o = (size_t)(32 + 16 * ks) * HW;
            ra[ks] = *(const float4*)(Ag + o);
#pragma unroll
            for (int j = 0; j < 5; ++j) rb[ks][j] = *(const float4*)(Bg + o + 64 * j);
        }
        __syncthreads();   // covers: prev acc->vol writes AND chunk-0 stage

        float acc[4][5][4];
#pragma unroll
        for (int i = 0; i < 4; ++i)
#pragma unroll
            for (int j = 0; j < 5; ++j)
#pragma unroll
                for (int k2 = 0; k2 < 4; ++k2) acc[i][j][k2] = 0.0f;

        // ---- mainloop: 2 ksteps per phase ----
        for (int c = 0; c < NCHUNK; ++c) {
            const uint32_t cur = sb + (uint32_t)((c & 1) * STAGE_BYTES);
            const uint32_t nxtoff = (uint32_t)(((c + 1) & 1) * STAGE_BYTES);

            uint32_t a0[4][4], b0[10];
            {
                const uint32_t ab = cur + OFF_A + laneA;
#pragma unroll
                for (int i = 0; i < 4; ++i) ldsm4t(a0[i], ab + 32u * i);
                const uint32_t bbq = cur + OFF_B + laneB + nbase;
                ldsm4t(b0 + 0, bbq); ldsm4t(b0 + 4, bbq + 32u); ldsm2t(b0 + 8, bbq + 64u);
            }
#pragma unroll
            for (int i = 0; i < 4; ++i)
#pragma unroll
                for (int j = 0; j < 5; ++j)
                    mma16816(acc[i][j], a0[i], b0 + 2 * j);

            // ---- previous tile's sampling, hidden under kstep-0 MMA drain ----
            if (c == 0 && have_prev)
                do_sampling(vol, out, pcent, t, pq0, phh, pbb);

            uint32_t a1[4][4], b1[10];
            {
                const uint32_t ab = cur + OFF_A + (uint32_t)KS_A + laneA;
#pragma unroll
                for (int i = 0; i < 4; ++i) ldsm4t(a1[i], ab + 32u * i);
                const uint32_t bbq = cur + OFF_B + (uint32_t)KS_B + laneB + nbase;
                ldsm4t(b1 + 0, bbq); ldsm4t(b1 + 4, bbq + 32u); ldsm2t(b1 + 8, bbq + 64u);
            }

            if (c + 1 < NCHUNK) {
#pragma unroll
                for (int ks = 0; ks < 2; ++ks) {
                    cvt_sts4(sts_a + nxtoff + (uint32_t)(ks * KS_A), ra[ks]);
#pragma unroll
                    for (int j = 0; j < 5; ++j)
                        cvt_sts4(sts_b + nxtoff + (uint32_t)(ks * KS_B) + 128u * j, rb[ks][j]);
                }
                if (c + 2 < NCHUNK) {
#pragma unroll
                    for (int ks = 0; ks < 2; ++ks) {
                        const size_t o = (size_t)((c + 2) * 32 + 16 * ks) * HW;
                        ra[ks] = *(const float4*)(Ag + o);
#pragma unroll
                        for (int j = 0; j < 5; ++j)
                            rb[ks][j] = *(const float4*)(Bg + o + 64 * j);
                    }
                }
            }

#pragma unroll
            for (int i = 0; i < 4; ++i)
#pragma unroll
                for (int j = 0; j < 5; ++j)
                    mma16816(acc[i][j], a1[i], b1 + 2 * j);

            __syncthreads();
        }

        // ---- next-tile pointers + chunk-0 LDGs (hidden under vol writes) ----
        const int ntile = tile + (int)gridDim.x;
        const bool have_next = (ntile < NTILES);
        if (have_next) {
            const int nqt = ntile % 5, nrm = ntile / 5;
            const int nhh = nrm % HH, nbb = nrm / HH, nq0 = nqt * MT;
            const float* nAg = fmap1 + ((size_t)nbb * CC + ch) * HW + (size_t)nhh * WW + nq0 + 4 * pos;
            const float* nBg = fmap2 + ((size_t)nbb * CC + ch) * HW + (size_t)nhh * WW + 4 * pos;
#pragma unroll
            for (int ks = 0; ks < 2; ++ks) {
                const size_t o = (size_t)(16 * ks) * HW;
                ra[ks] = *(const float4*)(nAg + o);
#pragma unroll
                for (int j = 0; j < 5; ++j) rb[ks][j] = *(const float4*)(nBg + o + 64 * j);
            }
            // save prev context, advance
            have_prev = true; pcent = cent; pq0 = q0; phh = hh; pbb = bb2;
            tile = ntile; q0 = nq0; hh = nhh; bb2 = nbb; Ag = nAg; Bg = nBg;
        }

        // ---- accumulators -> vol ----
        {
            const int mr = lid >> 2, nc0 = 2 * (lid & 3);
            const float s = 0.0625f;  // 1/sqrt(256)
#pragma unroll
            for (int i = 0; i < 4; ++i)
#pragma unroll
                for (int j = 0; j < 5; ++j) {
                    const int q = 16 * i + mr, v = 40 * wid + 8 * j + nc0;
                    *(float2*)&vol[q * VROW + GUARD + v] =
                        make_float2(acc[i][j][0] * s, acc[i][j][1] * s);
                    *(float2*)&vol[(q + 8) * VROW + GUARD + v] =
                        make_float2(acc[i][j][2] * s, acc[i][j][3] * s);
                }
        }

        if (!have_next) {
            __syncthreads();
            do_sampling(vol, out, cent, t, q0, hh, bb2);
            break;
        }
        // loop-top barrier (after chunk-0 staging) makes vol writes visible
        // before the deferred sampling at next phase 0.
    }
}

extern "C" void kernel_launch(void* const* d_in, const int* in_sizes, int n_in,
                              void* d_out, int out_size) {
    const float* fmap1 = (const float*)d_in[0];
    const float* fmap2 = (const float*)d_in[1];
    const float* cents = (const float*)d_in[2];
    float* out = (float*)d_out;

    cudaFuncSetAttribute(corr_hmma_kernel,
                         cudaFuncAttributeMaxDynamicSharedMemorySize, SMEM_BYTES);

    int dev = 0, sms = 148;
    cudaGetDevice(&dev);
    cudaDeviceGetAttribute(&sms, cudaDevAttrMultiProcessorCount, dev);
    if (sms > NTILES) sms = NTILES;

    corr_hmma_kernel<<<sms, NTH, SMEM_BYTES>>>(fmap1, fmap2, cents, out);
}